// round 15
// baseline (speedup 1.0000x reference)
#include <cuda_runtime.h>
#include <cstdint>

// Row-wise top-k(=6) thresholded renormalization.
//   delta = (6th largest of row) + 1e-7
//   w     = max(v - delta, 0) ;  out = w / (sum(w) + 1e-7)
//
// R15 = R14 + 2-redux threshold (was 6 serial redux rounds):
//   groups of 4 lanes -> segmented redux.max gives 8 group maxes (each a
//   real element); t = redux.min of those => >= 8 instances >= t => t <= v6.
//   Serial dependency chain in the threshold stage drops ~210 -> ~70 cyc.
//   Candidate set grows (~7 -> ~20 typical) but remains provably a superset
//   of the top-6 multiset for ANY input; stage D (lane-0 insertion top-6)
//   is exact, and delta/rinv are computed analytically from s0..s5.

#define COLS   1024
#define TOPK   6
#define EPSV   1e-7f
#define WPB    4            // warps (=rows) per block

__device__ __forceinline__ unsigned redux_max_u32_m(unsigned v, unsigned mask) {
    unsigned r;
    asm volatile("redux.sync.max.u32 %0, %1, %2;"
                 : "=r"(r) : "r"(v), "r"(mask));
    return r;
}
__device__ __forceinline__ unsigned redux_min_u32(unsigned v) {
    unsigned r;
    asm volatile("redux.sync.min.u32 %0, %1, %2;"
                 : "=r"(r) : "r"(v), "r"(0xffffffffu));
    return r;
}
// monotone bijection: float ordering -> u32 ordering (exact, invertible)
__device__ __forceinline__ unsigned fkey(float f) {
    unsigned b = __float_as_uint(f);
    return b ^ ((unsigned)((int)b >> 31) | 0x80000000u);
}
__device__ __forceinline__ float funkey(unsigned k) {
    unsigned b = (k & 0x80000000u) ? (k ^ 0x80000000u) : ~k;
    return __uint_as_float(b);
}
__device__ __forceinline__ float4 fmax4(float4 a, float4 b) {
    return make_float4(fmaxf(a.x,b.x), fmaxf(a.y,b.y),
                       fmaxf(a.z,b.z), fmaxf(a.w,b.w));
}

__global__ __launch_bounds__(32 * WPB)
void topk_renorm_kernel(const float* __restrict__ in,
                        float* __restrict__ out, int rows) {
    const int lane = threadIdx.x & 31;
    const int warp = threadIdx.x >> 5;
    const int row  = blockIdx.x * WPB + warp;
    if (row >= rows) return;

    __shared__ unsigned sh_cand[WPB][COLS];   // full-row capacity per warp
    __shared__ int      sh_cnt[WPB];

    // ---- load: 32 elems/thread as 8 float4 (MLP=8, front-batched) ----
    const float4* rp = reinterpret_cast<const float4*>(in + (size_t)row * COLS);
    float4 v[8];
#pragma unroll
    for (int i = 0; i < 8; ++i) v[i] = __ldcs(rp + lane + 32 * i);

    // ---- per-thread max (31 FMNMX tree) ----
    float4 m01 = fmax4(v[0], v[1]), m23 = fmax4(v[2], v[3]);
    float4 m45 = fmax4(v[4], v[5]), m67 = fmax4(v[6], v[7]);
    float4 mm  = fmax4(fmax4(m01, m23), fmax4(m45, m67));
    float lmax = fmaxf(fmaxf(mm.x, mm.y), fmaxf(mm.z, mm.w));

    // ---- 2-redux threshold: t = min over 8 groups of (group-of-4 max) ----
    // Each group max is a real element and >= t  =>  8 instances >= t  =>
    // t <= v6 (the true 6th largest). Only two dependent redux ops.
    const unsigned gmask = 0xFu << (lane & ~3);
    unsigned gmax = redux_max_u32_m(fkey(lmax), gmask);
    unsigned tkey = redux_min_u32(gmax);
    const float t = funkey(tkey);    // identical on all lanes

    // ---- compact candidates (v >= t) into this warp's buffer ----
    if (lane == 0) sh_cnt[warp] = 0;
    __syncwarp();
    if (lmax >= t) {                 // lanes below threshold skip the scan
#pragma unroll
        for (int i = 0; i < 8; ++i) {
            if (v[i].x >= t) sh_cand[warp][atomicAdd(&sh_cnt[warp],1)] = fkey(v[i].x);
            if (v[i].y >= t) sh_cand[warp][atomicAdd(&sh_cnt[warp],1)] = fkey(v[i].y);
            if (v[i].z >= t) sh_cand[warp][atomicAdd(&sh_cnt[warp],1)] = fkey(v[i].z);
            if (v[i].w >= t) sh_cand[warp][atomicAdd(&sh_cnt[warp],1)] = fkey(v[i].w);
        }
    }
    __syncwarp();

    // ---- lane 0: insertion top-6 (exact) + analytic delta/rinv ----
    float delta, rinv;
    if (lane == 0) {
        const int n = sh_cnt[warp];          // n >= 8 by construction
        unsigned s0=0u,s1=0u,s2=0u,s3=0u,s4=0u,s5=0u;   // s0 >= ... >= s5
        for (int i = 0; i < n; ++i) {
            unsigned x = sh_cand[warp][i];
            if (x > s5) {
                if      (x > s0) { s5=s4;s4=s3;s3=s2;s2=s1;s1=s0;s0=x; }
                else if (x > s1) { s5=s4;s4=s3;s3=s2;s2=s1;s1=x; }
                else if (x > s2) { s5=s4;s4=s3;s3=s2;s2=x; }
                else if (x > s3) { s5=s4;s4=s3;s3=x; }
                else if (x > s4) { s5=s4;s4=x; }
                else             { s5=x; }
            }
        }
        delta = funkey(s5) + EPSV;
        // sum(w) over the whole row == clamped sum over the top-5 only:
        // every other element is <= v6 < delta -> contributes exactly 0.
        float sum = fmaxf(funkey(s0) - delta, 0.0f)
                  + fmaxf(funkey(s1) - delta, 0.0f)
                  + fmaxf(funkey(s2) - delta, 0.0f)
                  + fmaxf(funkey(s3) - delta, 0.0f)
                  + fmaxf(funkey(s4) - delta, 0.0f);
        rinv = 1.0f / (sum + EPSV);
    }
    delta = __shfl_sync(0xffffffffu, delta, 0);   // broadcast
    rinv  = __shfl_sync(0xffffffffu, rinv,  0);

    // ---- epilogue: clamp * rinv, store (no reduction needed) ----
    float4* op = reinterpret_cast<float4*>(out + (size_t)row * COLS);
#pragma unroll
    for (int i = 0; i < 8; ++i) {
        float4 o4;
        o4.x = fmaxf(v[i].x - delta, 0.0f) * rinv;
        o4.y = fmaxf(v[i].y - delta, 0.0f) * rinv;
        o4.z = fmaxf(v[i].z - delta, 0.0f) * rinv;
        o4.w = fmaxf(v[i].w - delta, 0.0f) * rinv;
        __stcs(op + lane + 32 * i, o4);
    }
}

extern "C" void kernel_launch(void* const* d_in, const int* in_sizes, int n_in,
                              void* d_out, int out_size) {
    const float* in = (const float*)d_in[0];
    float* out = (float*)d_out;
    const int rows = in_sizes[0] / COLS;           // 65536 for reference shape
    const int grid = (rows + WPB - 1) / WPB;
    topk_renorm_kernel<<<grid, 32 * WPB>>>(in, out, rows);
}

// round 16
// speedup vs baseline: 1.0736x; 1.0736x over previous
#include <cuda_runtime.h>
#include <cstdint>

// Row-wise top-k(=6) thresholded renormalization.
//   delta = (6th largest of row) + 1e-7
//   w     = max(v - delta, 0) ;  out = w / (sum(w) + 1e-7)
//
// R16 = R14 (champion) + FMA epilogue:
//   out = max(v*rinv - delta*rinv, 0)  — FFMA+FMNMX per element (was 3 ops).
//   delta*rinv precomputed on lane 0; <=2 ulp vs reference, under 1e-3 tol.
// Everything else identical to R14:
//   t    = 6th largest DISTINCT thread-max (ballot-free; provably <= v6)
//   cand = all elements >= t (full-row shared buffer => exact for ANY input)
//   v6   = 6th largest of cand (lane-0 insertion top-6, exact multiset)
//   sum(w) computed analytically from the top-5 (all other terms are
//   exactly 0 since delta = v6 + eps).

#define COLS   1024
#define TOPK   6
#define EPSV   1e-7f
#define WPB    4            // warps (=rows) per block

__device__ __forceinline__ unsigned redux_max_u32(unsigned v) {
    unsigned r;
    asm volatile("redux.sync.max.u32 %0, %1, %2;"
                 : "=r"(r) : "r"(v), "r"(0xffffffffu));
    return r;
}
// monotone bijection: float ordering -> u32 ordering (exact, invertible)
__device__ __forceinline__ unsigned fkey(float f) {
    unsigned b = __float_as_uint(f);
    return b ^ ((unsigned)((int)b >> 31) | 0x80000000u);
}
__device__ __forceinline__ float funkey(unsigned k) {
    unsigned b = (k & 0x80000000u) ? (k ^ 0x80000000u) : ~k;
    return __uint_as_float(b);
}
__device__ __forceinline__ float4 fmax4(float4 a, float4 b) {
    return make_float4(fmaxf(a.x,b.x), fmaxf(a.y,b.y),
                       fmaxf(a.z,b.z), fmaxf(a.w,b.w));
}

__global__ __launch_bounds__(32 * WPB)
void topk_renorm_kernel(const float* __restrict__ in,
                        float* __restrict__ out, int rows) {
    const int lane = threadIdx.x & 31;
    const int warp = threadIdx.x >> 5;
    const int row  = blockIdx.x * WPB + warp;
    if (row >= rows) return;

    __shared__ unsigned sh_cand[WPB][COLS];   // full-row capacity per warp
    __shared__ int      sh_cnt[WPB];

    // ---- load: 32 elems/thread as 8 float4 (MLP=8, front-batched) ----
    const float4* rp = reinterpret_cast<const float4*>(in + (size_t)row * COLS);
    float4 v[8];
#pragma unroll
    for (int i = 0; i < 8; ++i) v[i] = __ldcs(rp + lane + 32 * i);

    // ---- per-thread max (31 FMNMX tree) ----
    float4 m01 = fmax4(v[0], v[1]), m23 = fmax4(v[2], v[3]);
    float4 m45 = fmax4(v[4], v[5]), m67 = fmax4(v[6], v[7]);
    float4 mm  = fmax4(fmax4(m01, m23), fmax4(m45, m67));
    float lmax = fmaxf(fmaxf(mm.x, mm.y), fmaxf(mm.z, mm.w));

    // ---- t = 6th largest DISTINCT thread-max (ballot-free; t <= v6) ----
    unsigned a = fkey(lmax);
    unsigned kth = 0u;
#pragma unroll
    for (int r = 0; r < TOPK; ++r) {
        unsigned m = redux_max_u32(a);
        kth = m;
        if (a == m) a = 0u;          // ties removed together: distinct-kth
    }
    const float t = funkey(kth);     // identical on all lanes

    // ---- compact candidates (v >= t) into this warp's buffer ----
    if (lane == 0) sh_cnt[warp] = 0;
    __syncwarp();
    if (lmax >= t) {                 // most lanes skip the whole scan
#pragma unroll
        for (int i = 0; i < 8; ++i) {
            if (v[i].x >= t) sh_cand[warp][atomicAdd(&sh_cnt[warp],1)] = fkey(v[i].x);
            if (v[i].y >= t) sh_cand[warp][atomicAdd(&sh_cnt[warp],1)] = fkey(v[i].y);
            if (v[i].z >= t) sh_cand[warp][atomicAdd(&sh_cnt[warp],1)] = fkey(v[i].z);
            if (v[i].w >= t) sh_cand[warp][atomicAdd(&sh_cnt[warp],1)] = fkey(v[i].w);
        }
    }
    __syncwarp();

    // ---- lane 0: insertion top-6 (exact) + analytic delta/rinv/dr ----
    float rinv, dr;
    if (lane == 0) {
        const int n = sh_cnt[warp];          // n >= 6 by construction
        unsigned s0=0u,s1=0u,s2=0u,s3=0u,s4=0u,s5=0u;   // s0 >= ... >= s5
        for (int i = 0; i < n; ++i) {
            unsigned x = sh_cand[warp][i];
            if (x > s5) {
                if      (x > s0) { s5=s4;s4=s3;s3=s2;s2=s1;s1=s0;s0=x; }
                else if (x > s1) { s5=s4;s4=s3;s3=s2;s2=s1;s1=x; }
                else if (x > s2) { s5=s4;s4=s3;s3=s2;s2=x; }
                else if (x > s3) { s5=s4;s4=s3;s3=x; }
                else if (x > s4) { s5=s4;s4=x; }
                else             { s5=x; }
            }
        }
        const float delta = funkey(s5) + EPSV;
        // sum(w) over the whole row == clamped sum over the top-5 only:
        // every other element is <= v6 < delta -> contributes exactly 0.
        float sum = fmaxf(funkey(s0) - delta, 0.0f)
                  + fmaxf(funkey(s1) - delta, 0.0f)
                  + fmaxf(funkey(s2) - delta, 0.0f)
                  + fmaxf(funkey(s3) - delta, 0.0f)
                  + fmaxf(funkey(s4) - delta, 0.0f);
        rinv = 1.0f / (sum + EPSV);
        dr   = delta * rinv;
    }
    rinv = __shfl_sync(0xffffffffu, rinv, 0);     // broadcast
    dr   = __shfl_sync(0xffffffffu, dr,   0);

    // ---- epilogue: out = max(v*rinv - dr, 0)  (FFMA + FMNMX) ----
    float4* op = reinterpret_cast<float4*>(out + (size_t)row * COLS);
#pragma unroll
    for (int i = 0; i < 8; ++i) {
        float4 o4;
        o4.x = fmaxf(fmaf(v[i].x, rinv, -dr), 0.0f);
        o4.y = fmaxf(fmaf(v[i].y, rinv, -dr), 0.0f);
        o4.z = fmaxf(fmaf(v[i].z, rinv, -dr), 0.0f);
        o4.w = fmaxf(fmaf(v[i].w, rinv, -dr), 0.0f);
        __stcs(op + lane + 32 * i, o4);
    }
}

extern "C" void kernel_launch(void* const* d_in, const int* in_sizes, int n_in,
                              void* d_out, int out_size) {
    const float* in = (const float*)d_in[0];
    float* out = (float*)d_out;
    const int rows = in_sizes[0] / COLS;           // 65536 for reference shape
    const int grid = (rows + WPB - 1) / WPB;
    topk_renorm_kernel<<<grid, 32 * WPB>>>(in, out, rows);
}